// round 1
// baseline (speedup 1.0000x reference)
#include <cuda_runtime.h>
#include <cstdint>

// Problem constants (fixed by the dataset)
#define NMAX 50048
#define FDIM 128
#define HEADS 4
#define GNUM 64
#define HID2 64
#define OUTD 10

// ---------------- scratch (no allocation allowed) ----------------
__device__ __align__(16) float g_hw [NMAX * FDIM];   // h = in @ W
__device__ __align__(16) float g_acc[NMAX * FDIM];   // unnormalized aggregation / exp buffer
__device__ __align__(16) float g_hsm[NMAX * FDIM];   // per-graph-softmaxed h (next layer input)
__device__ __align__(16) float g_als[NMAX * HEADS];
__device__ __align__(16) float g_ald[NMAX * HEADS];
__device__ __align__(16) float g_ssum[NMAX * HEADS];
__device__ __align__(16) float g_ge [NMAX];
__device__ __align__(16) float g_colsum[GNUM * FDIM];
__device__ __align__(16) float g_gatesum[GNUM];
__device__ __align__(16) float g_hg [GNUM * FDIM];
__device__ int g_idx64;

// ---------------- helpers ----------------
__device__ __forceinline__ int load_idx(const void* p, long long i, int f64) {
    return f64 ? (int)((const long long*)p)[i] : ((const int*)p)[i];
}

__device__ __forceinline__ void red_add_v4(float* ptr, float a, float b, float c, float d) {
    asm volatile("red.global.add.v4.f32 [%0], {%1,%2,%3,%4};"
                 :: "l"(ptr), "f"(a), "f"(b), "f"(c), "f"(d) : "memory");
}

// Detect whether index arrays are int64 (odd 32-bit words all zero) or int32.
__global__ void k_probe(const void* ei) {
    if (threadIdx.x == 0) {
        const int* w = (const int*)ei;
        int f = 1;
        for (int i = 0; i < 64; i++) if (w[2 * i + 1] != 0) { f = 0; break; }
        g_idx64 = f;
    }
}

__global__ void k_init(int zero_hg) {
    int t = blockIdx.x * blockDim.x + threadIdx.x;
    if (t < GNUM * FDIM) { g_colsum[t] = 0.f; if (zero_hg) g_hg[t] = 0.f; }
    if (t < GNUM) g_gatesum[t] = 0.f;
}

// ---------------- GEMM: out = A[N,128] @ W[128,128] -> g_hw ----------------
// Ain == nullptr means "use g_hsm" (layer 2 input).
__global__ void k_gemm(const float* __restrict__ Ain, const float* __restrict__ W, int N) {
    const float* A = Ain ? Ain : g_hsm;
    __shared__ __align__(16) float sx[16 * 128];
    int row0 = blockIdx.x * 16;
    float4* sx4 = (float4*)sx;
    const float4* A4 = (const float4*)A;
    for (int i = threadIdx.x; i < 512; i += 128) {
        int r = i >> 5;
        if (row0 + r < N) sx4[i] = A4[(long long)(row0 + r) * 32 + (i & 31)];
        else sx4[i] = make_float4(0.f, 0.f, 0.f, 0.f);
    }
    __syncthreads();
    int col = threadIdx.x;  // 0..127
    float acc[16];
#pragma unroll
    for (int r = 0; r < 16; r++) acc[r] = 0.f;
#pragma unroll 4
    for (int k = 0; k < 128; k++) {
        float w = W[k * 128 + col];
#pragma unroll
        for (int r = 0; r < 16; r++) acc[r] += sx[r * 128 + k] * w;
    }
#pragma unroll
    for (int r = 0; r < 16; r++) {
        int row = row0 + r;
        if (row < N) g_hw[(long long)row * 128 + col] = acc[r];
    }
}

// ---------------- per-node: attention logit pieces + self-loop init ----------
// warp per node. lane covers 4 features (float4); head = lane/8.
__global__ void k_node_prep(const float* __restrict__ a_src, const float* __restrict__ a_dst, int N) {
    int t = blockIdx.x * blockDim.x + threadIdx.x;
    int n = t >> 5, lane = t & 31;
    if (n >= N) return;
    int h = lane >> 3;
    float4 v = ((const float4*)(g_hw + (long long)n * 128))[lane];
    float4 a = ((const float4*)a_src)[lane];   // flat [128]; 4*lane == h*32 + 4*(lane%8)
    float4 b = ((const float4*)a_dst)[lane];
    float ps = v.x * a.x + v.y * a.y + v.z * a.z + v.w * a.w;
    float pd = v.x * b.x + v.y * b.y + v.z * b.z + v.w * b.w;
#pragma unroll
    for (int off = 4; off; off >>= 1) {
        ps += __shfl_xor_sync(0xffffffffu, ps, off);
        pd += __shfl_xor_sync(0xffffffffu, pd, off);
    }
    float lg = ps + pd;
    lg = lg > 0.f ? lg : 0.2f * lg;           // leaky_relu(0.2)
    float es = __expf(lg);                     // self-loop term (no max-shift needed)
    if ((lane & 7) == 0) {
        g_als[n * 4 + h] = ps;
        g_ald[n * 4 + h] = pd;
        g_ssum[n * 4 + h] = es;
    }
    float4 o = make_float4(es * v.x, es * v.y, es * v.z, es * v.w);
    ((float4*)(g_acc + (long long)n * 128))[lane] = o;
}

// ---------------- edge pass (single pass: weighted agg + softmax denom) ------
// warp per edge.
__global__ void k_edge(const void* __restrict__ ei, long long E, int N) {
    long long t = (long long)blockIdx.x * blockDim.x + threadIdx.x;
    long long e = t >> 5;
    int lane = (int)(t & 31);
    if (e >= E) return;
    int f64 = g_idx64;
    int s = load_idx(ei, e, f64);
    int d = load_idx(ei, E + e, f64);
    int h = lane >> 3;
    float lg = g_als[s * 4 + h] + g_ald[d * 4 + h];
    lg = lg > 0.f ? lg : 0.2f * lg;
    float w = __expf(lg);
    if ((lane & 7) == 0) atomicAdd(&g_ssum[d * 4 + h], w);
    float4 v = ((const float4*)(g_hw + (long long)s * 128))[lane];
    float* dst = g_acc + (long long)d * 128 + lane * 4;
    red_add_v4(dst, w * v.x, w * v.y, w * v.z, w * v.w);
}

// ---------------- normalize + bias + relu + exp (column softmax numerator) ---
// warp per node; writes exp(relu(h)) in place into g_acc; accumulates colsum.
__global__ void k_softcol(const float* __restrict__ bvec, const void* __restrict__ batch, int N) {
    int t = blockIdx.x * blockDim.x + threadIdx.x;
    int n = t >> 5, lane = t & 31;
    if (n >= N) return;
    int f64 = g_idx64;
    int g = load_idx(batch, n, f64);
    int h = lane >> 3;
    float4 v = ((const float4*)(g_acc + (long long)n * 128))[lane];
    float inv = __fdividef(1.f, g_ssum[n * 4 + h]);
    float4 b = ((const float4*)bvec)[lane];
    float4 u;
    u.x = fmaxf(v.x * inv + b.x, 0.f);
    u.y = fmaxf(v.y * inv + b.y, 0.f);
    u.z = fmaxf(v.z * inv + b.z, 0.f);
    u.w = fmaxf(v.w * inv + b.w, 0.f);
    float4 ev = make_float4(__expf(u.x), __expf(u.y), __expf(u.z), __expf(u.w));
    ((float4*)(g_acc + (long long)n * 128))[lane] = ev;
    red_add_v4(g_colsum + g * 128 + lane * 4, ev.x, ev.y, ev.z, ev.w);
}

// ---------------- column-softmax normalize + gate logits ---------------------
__global__ void k_norm_gate(const void* __restrict__ batch, const float* __restrict__ gate_w,
                            const float* __restrict__ gate_b, int N) {
    int t = blockIdx.x * blockDim.x + threadIdx.x;
    int n = t >> 5, lane = t & 31;
    if (n >= N) return;
    int f64 = g_idx64;
    int g = load_idx(batch, n, f64);
    float4 e = ((const float4*)(g_acc + (long long)n * 128))[lane];
    float4 c = ((const float4*)(g_colsum + g * 128))[lane];
    float4 hs = make_float4(__fdividef(e.x, c.x), __fdividef(e.y, c.y),
                            __fdividef(e.z, c.z), __fdividef(e.w, c.w));
    ((float4*)(g_hsm + (long long)n * 128))[lane] = hs;
    float4 gw = ((const float4*)gate_w)[lane];
    float p = hs.x * gw.x + hs.y * gw.y + hs.z * gw.z + hs.w * gw.w;
#pragma unroll
    for (int off = 16; off; off >>= 1) p += __shfl_xor_sync(0xffffffffu, p, off);
    if (lane == 0) {
        float ge = __expf(p + gate_b[0]);
        g_ge[n] = ge;
        atomicAdd(&g_gatesum[g], ge);
    }
}

// ---------------- gated pooling -> hg ----------------------------------------
__global__ void k_pool(const void* __restrict__ batch, int N) {
    int t = blockIdx.x * blockDim.x + threadIdx.x;
    int n = t >> 5, lane = t & 31;
    if (n >= N) return;
    int f64 = g_idx64;
    int g = load_idx(batch, n, f64);
    float w = __fdividef(g_ge[n], g_gatesum[g]);
    float4 hs = ((const float4*)(g_hsm + (long long)n * 128))[lane];
    red_add_v4(g_hg + g * 128 + lane * 4, w * hs.x, w * hs.y, w * hs.z, w * hs.w);
}

// ---------------- MLP head ----------------------------------------------------
__global__ void k_head(const float* __restrict__ lin_w, const float* __restrict__ lin_b,
                       const float* __restrict__ cls_w, const float* __restrict__ cls_b,
                       float* __restrict__ out) {
    int g = blockIdx.x;
    int j = threadIdx.x;
    __shared__ float sh[HID2];
    float a = lin_b[j];
#pragma unroll 4
    for (int k = 0; k < 128; k++) a += g_hg[g * 128 + k] * lin_w[k * HID2 + j];
    sh[j] = fmaxf(a, 0.f);
    __syncthreads();
    if (j < OUTD) {
        float o = cls_b[j];
#pragma unroll
        for (int k = 0; k < HID2; k++) o += sh[k] * cls_w[k * OUTD + j];
        out[g * OUTD + j] = o;
    }
}

// ---------------- launch ------------------------------------------------------
extern "C" void kernel_launch(void* const* d_in, const int* in_sizes, int n_in,
                              void* d_out, int out_size) {
    const float* x      = (const float*)d_in[0];
    const void*  ei     = d_in[1];
    const void*  batch  = d_in[2];
    const float* W1     = (const float*)d_in[3];
    const float* as1    = (const float*)d_in[4];
    const float* ad1    = (const float*)d_in[5];
    const float* b1     = (const float*)d_in[6];
    const float* W2     = (const float*)d_in[7];
    const float* as2    = (const float*)d_in[8];
    const float* ad2    = (const float*)d_in[9];
    const float* b2     = (const float*)d_in[10];
    const float* gate_w = (const float*)d_in[11];
    const float* gate_b = (const float*)d_in[12];
    const float* lin_w  = (const float*)d_in[13];
    const float* lin_b  = (const float*)d_in[14];
    const float* cls_w  = (const float*)d_in[15];
    const float* cls_b  = (const float*)d_in[16];
    float* out = (float*)d_out;

    int N = in_sizes[0] / FDIM;
    long long E = (long long)in_sizes[1] / 2;

    int nodeBlocks = (N + 7) / 8;                       // warp per node, 256 thr
    int edgeBlocks = (int)((E + 7) / 8);                // warp per edge, 256 thr

    k_probe<<<1, 32>>>(ei);

    // ---- layer 1 ----
    k_init<<<(GNUM * FDIM + 255) / 256, 256>>>(1);
    k_gemm<<<(N + 15) / 16, 128>>>(x, W1, N);
    k_node_prep<<<nodeBlocks, 256>>>(as1, ad1, N);
    k_edge<<<edgeBlocks, 256>>>(ei, E, N);
    k_softcol<<<nodeBlocks, 256>>>(b1, batch, N);
    k_norm_gate<<<nodeBlocks, 256>>>(batch, gate_w, gate_b, N);
    k_pool<<<nodeBlocks, 256>>>(batch, N);

    // ---- layer 2 ----
    k_init<<<(GNUM * FDIM + 255) / 256, 256>>>(0);
    k_gemm<<<(N + 15) / 16, 128>>>(nullptr, W2, N);
    k_node_prep<<<nodeBlocks, 256>>>(as2, ad2, N);
    k_edge<<<edgeBlocks, 256>>>(ei, E, N);
    k_softcol<<<nodeBlocks, 256>>>(b2, batch, N);
    k_norm_gate<<<nodeBlocks, 256>>>(batch, gate_w, gate_b, N);
    k_pool<<<nodeBlocks, 256>>>(batch, N);

    // ---- head ----
    k_head<<<GNUM, HID2>>>(lin_w, lin_b, cls_w, cls_b, out);
}

// round 2
// speedup vs baseline: 1.5133x; 1.5133x over previous
#include <cuda_runtime.h>
#include <cstdint>
#include <cstddef>

#define NMAX 50048
#define EMAX 1700000
#define FDIM 128
#define GNUM 64
#define HID2 64
#define OUTD 10

// ---------------- scratch ----------------
__device__ __align__(16) float g_hw [NMAX * FDIM];
__device__ __align__(16) float g_acc[NMAX * FDIM];
__device__ __align__(16) float g_hsm[NMAX * FDIM];
__device__ __align__(16) float g_als[NMAX * 4];
__device__ __align__(16) float g_ald[NMAX * 4];
__device__ __align__(16) float g_colsum[GNUM * FDIM];
__device__ __align__(16) float g_num[GNUM * FDIM];
__device__ __align__(16) float g_gatesum[GNUM];
__device__ __align__(16) float g_hg [GNUM * FDIM];
__device__ int g_deg[NMAX];
__device__ int g_off[NMAX + 1];
__device__ int g_cur[NMAX];
__device__ int g_csr[EMAX];
__device__ int g_idx64;

__device__ __forceinline__ int load_idx(const void* p, long long i, int f64) {
    return f64 ? (int)((const long long*)p)[i] : ((const int*)p)[i];
}
__device__ __forceinline__ void red_add_v4(float* ptr, float a, float b, float c, float d) {
    asm volatile("red.global.add.v4.f32 [%0], {%1,%2,%3,%4};"
                 :: "l"(ptr), "f"(a), "f"(b), "f"(c), "f"(d) : "memory");
}

__global__ void k_probe(const void* ei) {
    if (threadIdx.x == 0) {
        const int* w = (const int*)ei;
        int f = 1;
        for (int i = 0; i < 64; i++) if (w[2 * i + 1] != 0) { f = 0; break; }
        g_idx64 = f;
    }
}

// zero degree + per-layer accumulators + hg
__global__ void k_zero_pre(int N) {
    int t = blockIdx.x * blockDim.x + threadIdx.x;
    if (t < N) g_deg[t] = 0;
    if (t < GNUM * FDIM) { g_colsum[t] = 0.f; g_num[t] = 0.f; g_hg[t] = 0.f; }
    if (t < GNUM) g_gatesum[t] = 0.f;
}
__global__ void k_zero_layer() {
    int t = blockIdx.x * blockDim.x + threadIdx.x;
    if (t < GNUM * FDIM) { g_colsum[t] = 0.f; g_num[t] = 0.f; }
    if (t < GNUM) g_gatesum[t] = 0.f;
}

__global__ void k_hist(const void* __restrict__ ei, long long E) {
    long long t = (long long)blockIdx.x * blockDim.x + threadIdx.x;
    if (t >= E) return;
    int d = load_idx(ei, E + t, g_idx64);
    atomicAdd(&g_deg[d], 1);
}

// single-block exclusive scan of g_deg -> g_off, g_cur
__global__ void k_scan(int N) {
    __shared__ int sdata[1024];
    __shared__ int carry;
    if (threadIdx.x == 0) carry = 0;
    __syncthreads();
    for (int base = 0; base < N; base += 1024) {
        int i = base + threadIdx.x;
        int v = (i < N) ? g_deg[i] : 0;
        sdata[threadIdx.x] = v;
        __syncthreads();
        for (int off = 1; off < 1024; off <<= 1) {
            int t = (threadIdx.x >= off) ? sdata[threadIdx.x - off] : 0;
            __syncthreads();
            sdata[threadIdx.x] += t;
            __syncthreads();
        }
        int excl = sdata[threadIdx.x] - v + carry;
        if (i < N) { g_off[i] = excl; g_cur[i] = excl; }
        __syncthreads();
        if (threadIdx.x == 1023) carry += sdata[1023];
        __syncthreads();
    }
    if (threadIdx.x == 0) g_off[N] = carry;
}

__global__ void k_fill(const void* __restrict__ ei, long long E) {
    long long t = (long long)blockIdx.x * blockDim.x + threadIdx.x;
    if (t >= E) return;
    int f64 = g_idx64;
    int s = load_idx(ei, t, f64);
    int d = load_idx(ei, E + t, f64);
    int pos = atomicAdd(&g_cur[d], 1);
    g_csr[pos] = s;
}

// ---------------- GEMM: g_hw = A[N,128] @ W[128,128] ----------------
__global__ void k_gemm(const float* __restrict__ Ain, const float* __restrict__ W, int N) {
    const float* A = Ain ? Ain : g_hsm;
    __shared__ __align__(16) float sx[16 * 128];
    int row0 = blockIdx.x * 16;
    float4* sx4 = (float4*)sx;
    const float4* A4 = (const float4*)A;
    for (int i = threadIdx.x; i < 512; i += 128) {
        int r = i >> 5;
        if (row0 + r < N) sx4[i] = A4[(size_t)(row0 + r) * 32 + (i & 31)];
        else sx4[i] = make_float4(0.f, 0.f, 0.f, 0.f);
    }
    __syncthreads();
    int col = threadIdx.x;
    float acc[16];
#pragma unroll
    for (int r = 0; r < 16; r++) acc[r] = 0.f;
#pragma unroll 4
    for (int k = 0; k < 128; k++) {
        float w = W[k * 128 + col];
#pragma unroll
        for (int r = 0; r < 16; r++) acc[r] += sx[r * 128 + k] * w;
    }
#pragma unroll
    for (int r = 0; r < 16; r++) {
        int row = row0 + r;
        if (row < N) g_hw[(size_t)row * 128 + col] = acc[r];
    }
}

// ---------------- per-node attention logit pieces ----------------
__global__ void k_node_prep(const float* __restrict__ a_src, const float* __restrict__ a_dst, int N) {
    int t = blockIdx.x * blockDim.x + threadIdx.x;
    int n = t >> 5, lane = t & 31;
    if (n >= N) return;
    int h = lane >> 3;
    float4 v = ((const float4*)(g_hw + (size_t)n * 128))[lane];
    float4 a = ((const float4*)a_src)[lane];
    float4 b = ((const float4*)a_dst)[lane];
    float ps = v.x * a.x + v.y * a.y + v.z * a.z + v.w * a.w;
    float pd = v.x * b.x + v.y * b.y + v.z * b.z + v.w * b.w;
#pragma unroll
    for (int off = 4; off; off >>= 1) {
        ps += __shfl_xor_sync(0xffffffffu, ps, off);
        pd += __shfl_xor_sync(0xffffffffu, pd, off);
    }
    if ((lane & 7) == 0) {
        g_als[n * 4 + h] = ps;
        g_ald[n * 4 + h] = pd;
    }
}

// ---------------- aggregation: warp per dst (CSR gather) ----------------
// Fuses: edge softmax num+denom, self-loop, normalize, bias, relu, exp, colsum.
__global__ void k_agg(const float* __restrict__ bvec, const void* __restrict__ batch, int N) {
    int n = blockIdx.x * 8 + (threadIdx.x >> 5);
    int lane = threadIdx.x & 31;
    if (n >= N) return;
    const unsigned FULL = 0xffffffffu;
    int hf = lane >> 3;   // head in feature layout
    int hq = lane & 3;    // head in quad layout
    float ald_q = g_ald[n * 4 + hq];
    // self loop
    float lg = g_als[n * 4 + hq] + ald_q;
    lg = lg > 0.f ? lg : 0.2f * lg;
    float wq = __expf(lg);
    float ssum_q = wq;
    float wf = __shfl_sync(FULL, wq, hf);
    float4 v = ((const float4*)(g_hw + (size_t)n * 128))[lane];
    float4 acc = make_float4(wf * v.x, wf * v.y, wf * v.z, wf * v.w);

    int beg = g_off[n], end = g_off[n + 1];
    for (int j = beg; j < end; j += 8) {
        int rem = end - j;
        int et = lane >> 2;             // edge slot 0..7
        int s_e = 0; float wv = 0.f;
        if (et < rem) {
            s_e = g_csr[j + et];
            float l2 = g_als[s_e * 4 + hq] + ald_q;
            l2 = l2 > 0.f ? l2 : 0.2f * l2;
            wv = __expf(l2);
        }
        ssum_q += wv;
        int cnt = rem < 8 ? rem : 8;
#pragma unroll
        for (int t = 0; t < 8; t++) {
            if (t >= cnt) break;
            float w = __shfl_sync(FULL, wv, t * 4 + hf);
            int s = __shfl_sync(FULL, s_e, t * 4);
            float4 u = ((const float4*)(g_hw + (size_t)s * 128))[lane];
            acc.x += w * u.x; acc.y += w * u.y; acc.z += w * u.z; acc.w += w * u.w;
        }
    }
    // reduce ssum over same-hq lanes; broadcast to feature layout
#pragma unroll
    for (int off = 4; off < 32; off <<= 1) ssum_q += __shfl_xor_sync(FULL, ssum_q, off);
    float inv = __fdividef(1.f, __shfl_sync(FULL, ssum_q, hf));

    float4 b = ((const float4*)bvec)[lane];
    float4 u;
    u.x = fmaxf(acc.x * inv + b.x, 0.f);
    u.y = fmaxf(acc.y * inv + b.y, 0.f);
    u.z = fmaxf(acc.z * inv + b.z, 0.f);
    u.w = fmaxf(acc.w * inv + b.w, 0.f);
    float4 ev = make_float4(__expf(u.x), __expf(u.y), __expf(u.z), __expf(u.w));
    ((float4*)(g_acc + (size_t)n * 128))[lane] = ev;
    int g = load_idx(batch, n, g_idx64);
    red_add_v4(g_colsum + g * 128 + lane * 4, ev.x, ev.y, ev.z, ev.w);
}

// ---------------- column softmax + gate + weighted pool accumulation ----------
__global__ void k_ngp(const void* __restrict__ batch, const float* __restrict__ gate_w,
                      const float* __restrict__ gate_b, int N) {
    int t = blockIdx.x * blockDim.x + threadIdx.x;
    int n = t >> 5, lane = t & 31;
    if (n >= N) return;
    const unsigned FULL = 0xffffffffu;
    int g = load_idx(batch, n, g_idx64);
    float4 e = ((const float4*)(g_acc + (size_t)n * 128))[lane];
    float4 c = ((const float4*)(g_colsum + g * 128))[lane];
    float4 hs = make_float4(__fdividef(e.x, c.x), __fdividef(e.y, c.y),
                            __fdividef(e.z, c.z), __fdividef(e.w, c.w));
    ((float4*)(g_hsm + (size_t)n * 128))[lane] = hs;
    float4 gw = ((const float4*)gate_w)[lane];
    float p = hs.x * gw.x + hs.y * gw.y + hs.z * gw.z + hs.w * gw.w;
#pragma unroll
    for (int off = 16; off; off >>= 1) p += __shfl_xor_sync(FULL, p, off);
    float ge = __expf(p + gate_b[0]);
    red_add_v4(g_num + g * 128 + lane * 4, ge * hs.x, ge * hs.y, ge * hs.z, ge * hs.w);
    if (lane == 0) atomicAdd(&g_gatesum[g], ge);
}

__global__ void k_fin() {
    int t = blockIdx.x * blockDim.x + threadIdx.x;
    if (t < GNUM * FDIM)
        g_hg[t] += g_num[t] * __fdividef(1.f, g_gatesum[t >> 7]);
}

// ---------------- MLP head ----------------
__global__ void k_head(const float* __restrict__ lin_w, const float* __restrict__ lin_b,
                       const float* __restrict__ cls_w, const float* __restrict__ cls_b,
                       float* __restrict__ out) {
    int g = blockIdx.x;
    int j = threadIdx.x;
    __shared__ float sh[HID2];
    float a = lin_b[j];
#pragma unroll 4
    for (int k = 0; k < 128; k++) a += g_hg[g * 128 + k] * lin_w[k * HID2 + j];
    sh[j] = fmaxf(a, 0.f);
    __syncthreads();
    if (j < OUTD) {
        float o = cls_b[j];
#pragma unroll
        for (int k = 0; k < HID2; k++) o += sh[k] * cls_w[k * OUTD + j];
        out[g * OUTD + j] = o;
    }
}

// ---------------- launch ----------------
extern "C" void kernel_launch(void* const* d_in, const int* in_sizes, int n_in,
                              void* d_out, int out_size) {
    const float* x      = (const float*)d_in[0];
    const void*  ei     = d_in[1];
    const void*  batch  = d_in[2];
    const float* W1     = (const float*)d_in[3];
    const float* as1    = (const float*)d_in[4];
    const float* ad1    = (const float*)d_in[5];
    const float* b1     = (const float*)d_in[6];
    const float* W2     = (const float*)d_in[7];
    const float* as2    = (const float*)d_in[8];
    const float* ad2    = (const float*)d_in[9];
    const float* b2     = (const float*)d_in[10];
    const float* gate_w = (const float*)d_in[11];
    const float* gate_b = (const float*)d_in[12];
    const float* lin_w  = (const float*)d_in[13];
    const float* lin_b  = (const float*)d_in[14];
    const float* cls_w  = (const float*)d_in[15];
    const float* cls_b  = (const float*)d_in[16];
    float* out = (float*)d_out;

    int N = in_sizes[0] / FDIM;
    long long E = (long long)in_sizes[1] / 2;

    int nodeBlocks = (N + 7) / 8;
    int edgeBlocks = (int)((E + 255) / 256);
    int zgrid = (N > GNUM * FDIM ? N : GNUM * FDIM);

    k_probe<<<1, 32>>>(ei);
    k_zero_pre<<<(zgrid + 255) / 256, 256>>>(N);
    k_hist<<<edgeBlocks, 256>>>(ei, E);
    k_scan<<<1, 1024>>>(N);
    k_fill<<<edgeBlocks, 256>>>(ei, E);

    // ---- layer 1 ----
    k_gemm<<<(N + 15) / 16, 128>>>(x, W1, N);
    k_node_prep<<<nodeBlocks, 256>>>(as1, ad1, N);
    k_agg<<<nodeBlocks, 256>>>(b1, batch, N);
    k_ngp<<<nodeBlocks, 256>>>(batch, gate_w, gate_b, N);
    k_fin<<<(GNUM * FDIM + 255) / 256, 256>>>();

    // ---- layer 2 ----
    k_zero_layer<<<(GNUM * FDIM + 255) / 256, 256>>>();
    k_gemm<<<(N + 15) / 16, 128>>>(nullptr, W2, N);
    k_node_prep<<<nodeBlocks, 256>>>(as2, ad2, N);
    k_agg<<<nodeBlocks, 256>>>(b2, batch, N);
    k_ngp<<<nodeBlocks, 256>>>(batch, gate_w, gate_b, N);
    k_fin<<<(GNUM * FDIM + 255) / 256, 256>>>();

    k_head<<<GNUM, HID2>>>(lin_w, lin_b, cls_w, cls_b, out);
}